// round 6
// baseline (speedup 1.0000x reference)
#include <cuda_runtime.h>

#define NF   128
#define NSEG 4096
#define MAXN 100000
#define MAXE 1000000

// ---- scratch (device globals: no runtime allocation allowed) ----
__device__ float    g_Pj[MAXN * NF];
__device__ float    g_Pi[MAXN * NF];    // holds Pi + bias (bias folded in epilogue)
__device__ float    g_alpha[MAXE];
__device__ unsigned g_segmax[NSEG];
__device__ float    g_segsum[NSEG];

// monotone float<->uint encoding so atomicMax works on signed floats
__device__ __forceinline__ unsigned fenc(float f) {
    unsigned b = __float_as_uint(f);
    return (b & 0x80000000u) ? ~b : (b | 0x80000000u);
}
__device__ __forceinline__ float fdec(unsigned u) {
    return __uint_as_float((u & 0x80000000u) ? (u & 0x7FFFFFFFu) : ~u);
}

__global__ void init_kernel() {
    int i = blockIdx.x * blockDim.x + threadIdx.x;
    if (i < NSEG) { g_segmax[i] = 0u; g_segsum[i] = 0.0f; }
}

// ---------------------------------------------------------------------------
// Projection GEMM: P[n, c] = sum_k X[n, k] * W[k, c],  K = N = 128.
// blockIdx.y selects (x_j,w_j)->g_Pj or (x_i,w_i)->g_Pi (+bias fold).
// 256 threads -> 128x128 tile, 8x8 thread tile. FFMA-bound.
// ---------------------------------------------------------------------------
__global__ __launch_bounds__(256)
void proj_kernel(const float* __restrict__ Xj, const float* __restrict__ Wj,
                 const float* __restrict__ Xi, const float* __restrict__ Wi,
                 const float* __restrict__ bias, int nrows) {
    const bool addb = (blockIdx.y == 1);
    const float* __restrict__ X = addb ? Xi : Xj;
    const float* __restrict__ W = addb ? Wi : Wj;
    float* __restrict__ P = addb ? g_Pi : g_Pj;

    __shared__ float xsT[32 * 129];   // [k][row], padded
    __shared__ float ws [32 * NF];    // [k][c]

    const int tid = threadIdx.x;
    const int tx  = tid & 15;
    const int ty  = tid >> 4;
    const int rowBase = blockIdx.x * 128;

    float acc[8][8];
#pragma unroll
    for (int i = 0; i < 8; i++)
#pragma unroll
        for (int j = 0; j < 8; j++) acc[i][j] = 0.0f;

    for (int kk = 0; kk < NF; kk += 32) {
#pragma unroll
        for (int p = 0; p < 4; p++) {
            int idx = p * 256 + tid;
            int row = idx >> 3;
            int kq  = idx & 7;
            int gr  = rowBase + row;
            float4 v = make_float4(0.f, 0.f, 0.f, 0.f);
            if (gr < nrows)
                v = *reinterpret_cast<const float4*>(X + gr * NF + kk + kq * 4);
            xsT[(kq * 4 + 0) * 129 + row] = v.x;
            xsT[(kq * 4 + 1) * 129 + row] = v.y;
            xsT[(kq * 4 + 2) * 129 + row] = v.z;
            xsT[(kq * 4 + 3) * 129 + row] = v.w;
        }
#pragma unroll
        for (int p = 0; p < 4; p++) {
            int idx = p * 256 + tid;
            int k  = idx >> 5;
            int cq = idx & 31;
            *reinterpret_cast<float4*>(ws + k * NF + cq * 4) =
                *reinterpret_cast<const float4*>(W + (kk + k) * NF + cq * 4);
        }
        __syncthreads();

#pragma unroll
        for (int k = 0; k < 32; k++) {
            float xv[8];
#pragma unroll
            for (int i = 0; i < 8; i++) xv[i] = xsT[k * 129 + ty * 8 + i];
            float4 w0 = *reinterpret_cast<const float4*>(ws + k * NF + tx * 4);
            float4 w1 = *reinterpret_cast<const float4*>(ws + k * NF + 64 + tx * 4);
#pragma unroll
            for (int i = 0; i < 8; i++) {
                acc[i][0] += xv[i] * w0.x;
                acc[i][1] += xv[i] * w0.y;
                acc[i][2] += xv[i] * w0.z;
                acc[i][3] += xv[i] * w0.w;
                acc[i][4] += xv[i] * w1.x;
                acc[i][5] += xv[i] * w1.y;
                acc[i][6] += xv[i] * w1.z;
                acc[i][7] += xv[i] * w1.w;
            }
        }
        __syncthreads();
    }

    float4 bv0 = make_float4(0.f, 0.f, 0.f, 0.f), bv1 = bv0;
    if (addb) {
        bv0 = *reinterpret_cast<const float4*>(bias + tx * 4);
        bv1 = *reinterpret_cast<const float4*>(bias + 64 + tx * 4);
    }
#pragma unroll
    for (int i = 0; i < 8; i++) {
        int gr = rowBase + ty * 8 + i;
        if (gr < nrows) {
            *reinterpret_cast<float4*>(P + gr * NF + tx * 4) =
                make_float4(acc[i][0] + bv0.x, acc[i][1] + bv0.y,
                            acc[i][2] + bv0.z, acc[i][3] + bv0.w);
            *reinterpret_cast<float4*>(P + gr * NF + 64 + tx * 4) =
                make_float4(acc[i][4] + bv1.x, acc[i][5] + bv1.y,
                            acc[i][6] + bv1.z, acc[i][7] + bv1.w);
        }
    }
}

// dot(PReLU(A+B), Wv) over a float4 slice
__device__ __forceinline__ float dprelu4(float4 A, float4 B, float4 Wv, float pw) {
    float h, s;
    h = A.x + B.x; h = (h >= 0.f) ? h : pw * h; s  = h * Wv.x;
    h = A.y + B.y; h = (h >= 0.f) ? h : pw * h; s += h * Wv.y;
    h = A.z + B.z; h = (h >= 0.f) ? h : pw * h; s += h * Wv.z;
    h = A.w + B.w; h = (h >= 0.f) ? h : pw * h; s += h * Wv.w;
    return s;
}

// ---------------------------------------------------------------------------
// alpha[e] = PReLU(Pj[src] + Pi'[dst]) . mlpW + mlpb   (bias already in Pi')
// One warp processes 4 consecutive edges SERIALLY; lane owns feature lane*4.
// Every row gather = one LDG.128, 32 consecutive 16B lanes -> 4 wf (minimum).
// All 8 gathers issued before consumption (MLP=8). mlpW/prelu/mlpb loaded
// once per warp; indices via 3 broadcast int4 loads; coalesced alpha store.
// Fused segmented max (sorted seg ids): lane 0 folds runs, ~1 atomic/warp.
// ---------------------------------------------------------------------------
__global__ __launch_bounds__(256)
void edge_alpha_kernel(const int* __restrict__ ei,
                       const int* __restrict__ seg,
                       const float* __restrict__ prelu_w,
                       const float* __restrict__ mlpW,
                       const float* __restrict__ mlpb, int E) {
    const int warp = (blockIdx.x * blockDim.x + threadIdx.x) >> 5;
    const int lane = threadIdx.x & 31;
    const int e0   = warp * 4;
    if (e0 >= E) return;

    const float4 w  = reinterpret_cast<const float4*>(mlpW)[lane];
    const float  pw = prelu_w[0];
    const float  mb = mlpb[0];

    int s0, s1, s2, s3, d0, d1, d2, d3, g0, g1, g2, g3, nval;
    if (((E & 3) == 0) && (e0 + 4 <= E)) {
        int4 sv = *reinterpret_cast<const int4*>(ei + e0);
        int4 dv = *reinterpret_cast<const int4*>(ei + E + e0);
        int4 gv = *reinterpret_cast<const int4*>(seg + e0);
        s0 = sv.x; s1 = sv.y; s2 = sv.z; s3 = sv.w;
        d0 = dv.x; d1 = dv.y; d2 = dv.z; d3 = dv.w;
        g0 = gv.x; g1 = gv.y; g2 = gv.z; g3 = gv.w;
        nval = 4;
    } else {
        nval = E - e0; if (nval > 4) nval = 4;
        s0 = ei[e0];     d0 = ei[E + e0];     g0 = seg[e0];
        s1 = (nval > 1) ? ei[e0 + 1] : s0;
        d1 = (nval > 1) ? ei[E + e0 + 1] : d0;
        g1 = (nval > 1) ? seg[e0 + 1] : g0;
        s2 = (nval > 2) ? ei[e0 + 2] : s0;
        d2 = (nval > 2) ? ei[E + e0 + 2] : d0;
        g2 = (nval > 2) ? seg[e0 + 2] : g0;
        s3 = (nval > 3) ? ei[e0 + 3] : s0;
        d3 = (nval > 3) ? ei[E + e0 + 3] : d0;
        g3 = (nval > 3) ? seg[e0 + 3] : g0;
    }

    // issue all 8 coalesced row gathers up front (MLP=8)
    const float4* fPj = reinterpret_cast<const float4*>(g_Pj);
    const float4* fPi = reinterpret_cast<const float4*>(g_Pi);
    float4 a0 = fPj[(size_t)s0 * 32 + lane];
    float4 a1 = fPj[(size_t)s1 * 32 + lane];
    float4 a2 = fPj[(size_t)s2 * 32 + lane];
    float4 a3 = fPj[(size_t)s3 * 32 + lane];
    float4 b0 = fPi[(size_t)d0 * 32 + lane];
    float4 b1 = fPi[(size_t)d1 * 32 + lane];
    float4 b2 = fPi[(size_t)d2 * 32 + lane];
    float4 b3 = fPi[(size_t)d3 * 32 + lane];

    float r0 = dprelu4(a0, b0, w, pw);
    float r1 = dprelu4(a1, b1, w, pw);
    float r2 = dprelu4(a2, b2, w, pw);
    float r3 = dprelu4(a3, b3, w, pw);

    // four independent 32-lane xor reductions (interleaved for ILP)
#pragma unroll
    for (int o = 16; o > 0; o >>= 1) {
        r0 += __shfl_xor_sync(0xffffffffu, r0, o);
        r1 += __shfl_xor_sync(0xffffffffu, r1, o);
        r2 += __shfl_xor_sync(0xffffffffu, r2, o);
        r3 += __shfl_xor_sync(0xffffffffu, r3, o);
    }
    const float al0 = r0 + mb, al1 = r1 + mb, al2 = r2 + mb, al3 = r3 + mb;

    // coalesced alpha store: lanes 0..3 write the 4 edges
    float myA = (lane == 0) ? al0 : (lane == 1) ? al1 : (lane == 2) ? al2 : al3;
    if (lane < nval) g_alpha[e0 + lane] = myA;

    // fused segmented max: lane 0 folds runs across the 4 edges
    if (lane == 0) {
        float m = al0; int cs = g0;
        if (nval > 1) {
            if (g1 == cs) m = fmaxf(m, al1);
            else { atomicMax(&g_segmax[cs], fenc(m)); cs = g1; m = al1; }
        }
        if (nval > 2) {
            if (g2 == cs) m = fmaxf(m, al2);
            else { atomicMax(&g_segmax[cs], fenc(m)); cs = g2; m = al2; }
        }
        if (nval > 3) {
            if (g3 == cs) m = fmaxf(m, al3);
            else { atomicMax(&g_segmax[cs], fenc(m)); cs = g3; m = al3; }
        }
        atomicMax(&g_segmax[cs], fenc(m));
    }
}

// e = exp(alpha - segmax); store to out; warp-segmented suffix-sum + atomicAdd
__global__ __launch_bounds__(256)
void expsum_kernel(const int* __restrict__ seg, float* __restrict__ out, int E) {
    int i    = blockIdx.x * blockDim.x + threadIdx.x;
    int lane = threadIdx.x & 31;
    float e = 0.0f;
    int   s = -1;
    if (i < E) {
        s = seg[i];
        float m = fdec(g_segmax[s]);
        e = __expf(g_alpha[i] - m);
        out[i] = e;
    }
    float sum = e;
#pragma unroll
    for (int o = 1; o < 32; o <<= 1) {
        float av = __shfl_down_sync(0xffffffffu, sum, o);
        int   sv = __shfl_down_sync(0xffffffffu, s, o);
        if (lane + o < 32 && sv == s) sum += av;
    }
    int sp = __shfl_up_sync(0xffffffffu, s, 1);
    bool head = (lane == 0) || (sp != s);
    if (i < E && head) atomicAdd(&g_segsum[s], sum);
}

__global__ __launch_bounds__(256)
void norm_kernel(const int* __restrict__ seg, float* __restrict__ out, int E) {
    int i = blockIdx.x * blockDim.x + threadIdx.x;
    if (i < E) out[i] = out[i] / (g_segsum[seg[i]] + 1e-16f);
}

// ---------------------------------------------------------------------------
extern "C" void kernel_launch(void* const* d_in, const int* in_sizes, int n_in,
                              void* d_out, int out_size) {
    const float* x_j   = (const float*)d_in[0];
    const float* x_i   = (const float*)d_in[1];
    const int*   ei    = (const int*)  d_in[2];
    const int*   seg   = (const int*)  d_in[3];
    const float* w_j   = (const float*)d_in[4];
    const float* w_i   = (const float*)d_in[5];
    const float* bias  = (const float*)d_in[6];
    const float* prelu = (const float*)d_in[7];
    const float* mlpW  = (const float*)d_in[8];
    const float* mlpb  = (const float*)d_in[9];

    int nnodes = in_sizes[0] / NF;
    int E      = in_sizes[3];
    float* out = (float*)d_out;

    init_kernel<<<(NSEG + 255) / 256, 256>>>();

    dim3 pg((nnodes + 127) / 128, 2);
    proj_kernel<<<pg, 256>>>(x_j, w_j, x_i, w_i, bias, nnodes);

    // 4 edges per warp, serially
    long long nwarps = (E + 3) / 4;
    long long nthreads = nwarps * 32;
    edge_alpha_kernel<<<(unsigned)((nthreads + 255) / 256), 256>>>(
        ei, seg, prelu, mlpW, mlpb, E);

    int eb = (E + 255) / 256;
    expsum_kernel<<<eb, 256>>>(seg, out, E);
    norm_kernel  <<<eb, 256>>>(seg, out, E);
}